// round 4
// baseline (speedup 1.0000x reference)
#include <cuda_runtime.h>

#define H_IMG 1080
#define W_IMG 1920
#define GY 16
#define GX 16
#define GW 8
#define NPIX (H_IMG * W_IMG)

#define BX 160                  // threads per block (5 warps)
#define PXT 4                   // consecutive pixels per thread
#define STRIP (BX * PXT)        // 640 pixels per strip
#define BLK_PER_ROW (W_IMG / STRIP)  // 3
#define NC 7                    // x-cells covered by one strip

#define SX (15.0f / 1919.0f)
#define SY (15.0f / 1079.0f)

__global__ __launch_bounds__(BX) void bilateral_grid_kernel(
    const float* __restrict__ rgb,
    const float* __restrict__ grids,
    const int*   __restrict__ idxp,
    float*       __restrict__ out)
{
    __shared__ __align__(16) float g2[NC * GW * 12];   // 672 floats = 168 float4

    const int tid   = threadIdx.x;
    const int row   = blockIdx.y;
    const int xpix0 = blockIdx.x * STRIP;

    // ---- prefetch rgb (independent of smem build) ----
    const int x0pix = xpix0 + tid * PXT;
    const int n0    = row * W_IMG + x0pix;
    float4 r4 = *reinterpret_cast<const float4*>(rgb + n0);
    float4 g4 = *reinterpret_cast<const float4*>(rgb + NPIX + n0);
    float4 b4 = *reinterpret_cast<const float4*>(rgb + 2 * NPIX + n0);

    // ---- block-uniform y lerp ----
    float gyv = (float)row * SY;
    float fy  = floorf(gyv);
    float wy  = gyv - fy;
    int y0 = min((int)fy, GY - 1);
    int y1 = min(y0 + 1, GY - 1);
    float wy0 = 1.0f - wy, wy1 = wy;

    const float* grid = grids + (size_t)idxp[0] * (GY * GX * GW * 12);
    int xbase = (int)((float)xpix0 * SX);

    // ---- vectorized g2 build: 168 float4 items ----
    for (int t = tid; t < NC * GW * 3; t += BX) {
        int xq  = t / (GW * 3);
        int rem = t - xq * (GW * 3);
        int zq  = rem / 3;
        int c4  = rem - zq * 3;
        int xc  = min(xbase + xq, GX - 1);
        const float4* pa = reinterpret_cast<const float4*>(
            grid + ((size_t)(y0 * GX + xc) * GW + zq) * 12) + c4;
        const float4* pb = reinterpret_cast<const float4*>(
            grid + ((size_t)(y1 * GX + xc) * GW + zq) * 12) + c4;
        float4 a = __ldg(pa);
        float4 b = __ldg(pb);
        float4 o;
        o.x = wy0 * a.x + wy1 * b.x;
        o.y = wy0 * a.y + wy1 * b.y;
        o.z = wy0 * a.z + wy1 * b.z;
        o.w = wy0 * a.w + wy1 * b.w;
        reinterpret_cast<float4*>(g2)[t] = o;
    }
    __syncthreads();

    const float rr[PXT] = {r4.x, r4.y, r4.z, r4.w};
    const float gg[PXT] = {g4.x, g4.y, g4.z, g4.w};
    const float bb[PXT] = {b4.x, b4.y, b4.z, b4.w};

    float res12[PXT * 3];
    float4* aout = reinterpret_cast<float4*>(out) + (size_t)n0 * 3;

    #pragma unroll
    for (int k = 0; k < PXT; k++) {
        const int x = x0pix + k;
        float r = rr[k], g = gg[k], b = bb[k];
        float gray = 0.299f * r + 0.587f * g + 0.114f * b;

        float gxv = (float)x * SX;
        float fx  = floorf(gxv);
        float wx  = gxv - fx;
        int xc0 = min((int)fx, GX - 1);
        int xc1 = min(xc0 + 1, GX - 1);
        int x0l = xc0 - xbase;
        int x1l = xc1 - xbase;

        float gz = __saturatef(gray) * (float)(GW - 1);
        float fz = floorf(gz);
        float wz = gz - fz;
        int z0 = min(max((int)fz, 0), GW - 1);
        int z1 = min(z0 + 1, GW - 1);

        float w00 = (1.0f - wx) * (1.0f - wz);
        float w01 = (1.0f - wx) * wz;
        float w10 = wx * (1.0f - wz);
        float w11 = wx * wz;

        const float4* c00 = reinterpret_cast<const float4*>(g2 + (x0l * GW + z0) * 12);
        const float4* c01 = reinterpret_cast<const float4*>(g2 + (x0l * GW + z1) * 12);
        const float4* c10 = reinterpret_cast<const float4*>(g2 + (x1l * GW + z0) * 12);
        const float4* c11 = reinterpret_cast<const float4*>(g2 + (x1l * GW + z1) * 12);

        float4 a0, a1, a2;
        {
            float4 p00, p01, p10, p11;
            p00 = c00[0]; p01 = c01[0]; p10 = c10[0]; p11 = c11[0];
            a0.x = w00*p00.x + w01*p01.x + w10*p10.x + w11*p11.x;
            a0.y = w00*p00.y + w01*p01.y + w10*p10.y + w11*p11.y;
            a0.z = w00*p00.z + w01*p01.z + w10*p10.z + w11*p11.z;
            a0.w = w00*p00.w + w01*p01.w + w10*p10.w + w11*p11.w;
            p00 = c00[1]; p01 = c01[1]; p10 = c10[1]; p11 = c11[1];
            a1.x = w00*p00.x + w01*p01.x + w10*p10.x + w11*p11.x;
            a1.y = w00*p00.y + w01*p01.y + w10*p10.y + w11*p11.y;
            a1.z = w00*p00.z + w01*p01.z + w10*p10.z + w11*p11.z;
            a1.w = w00*p00.w + w01*p01.w + w10*p10.w + w11*p11.w;
            p00 = c00[2]; p01 = c01[2]; p10 = c10[2]; p11 = c11[2];
            a2.x = w00*p00.x + w01*p01.x + w10*p10.x + w11*p11.x;
            a2.y = w00*p00.y + w01*p01.y + w10*p10.y + w11*p11.y;
            a2.z = w00*p00.z + w01*p01.z + w10*p10.z + w11*p11.z;
            a2.w = w00*p00.w + w01*p01.w + w10*p10.w + w11*p11.w;
        }

        aout[k * 3 + 0] = a0;
        aout[k * 3 + 1] = a1;
        aout[k * 3 + 2] = a2;

        res12[k * 3 + 0] = a0.x * r + a0.y * g + a0.z * b + a0.w;
        res12[k * 3 + 1] = a1.x * r + a1.y * g + a1.z * b + a1.w;
        res12[k * 3 + 2] = a2.x * r + a2.y * g + a2.z * b + a2.w;
    }

    // res_rgb: 12 consecutive floats per thread, 48B-aligned -> 3x STG.128
    float4* rout = reinterpret_cast<float4*>(out + (size_t)12 * NPIX + (size_t)n0 * 3);
    rout[0] = make_float4(res12[0], res12[1], res12[2],  res12[3]);
    rout[1] = make_float4(res12[4], res12[5], res12[6],  res12[7]);
    rout[2] = make_float4(res12[8], res12[9], res12[10], res12[11]);
}

extern "C" void kernel_launch(void* const* d_in, const int* in_sizes, int n_in,
                              void* d_out, int out_size) {
    const float* rgb   = (const float*)d_in[0];
    const float* grids = (const float*)d_in[1];
    const int*   idx   = (const int*)d_in[2];
    float* out = (float*)d_out;

    dim3 grid(BLK_PER_ROW, H_IMG);
    bilateral_grid_kernel<<<grid, BX>>>(rgb, grids, idx, out);
}

// round 5
// speedup vs baseline: 1.7517x; 1.7517x over previous
#include <cuda_runtime.h>

#define H_IMG 1080
#define W_IMG 1920
#define GY 16
#define GX 16
#define GW 8
#define NPIX (H_IMG * W_IMG)

#define BX 256                  // threads per block
#define PXT 2                   // pixels per thread, strided by BX
#define STRIP (BX * PXT)        // 512 pixels per strip
#define BLK_PER_ROW (W_IMG / STRIP)  // 3.75 -> need ceil; 1920/512 = 3.75
#define NC 6                    // x-cells covered by one strip

#define SX (15.0f / 1919.0f)
#define SY (15.0f / 1079.0f)

__global__ __launch_bounds__(BX) void bilateral_grid_kernel(
    const float* __restrict__ rgb,
    const float* __restrict__ grids,
    const int*   __restrict__ idxp,
    float*       __restrict__ out)
{
    __shared__ __align__(16) float g2[NC * GW * 12];   // 576 floats = 144 float4

    const int tid   = threadIdx.x;
    const int row   = blockIdx.y;
    const int xpix0 = blockIdx.x * STRIP;

    // ---- prefetch rgb early (strided: lanes adjacent -> coalesced) ----
    const int x0p = xpix0 + tid;
    const int x1p = x0p + BX;
    const int nA  = row * W_IMG + x0p;
    const int nB  = nA + BX;
    bool hasB = (x1p < W_IMG);

    float rA = __ldcs(rgb + nA);
    float gA = __ldcs(rgb + NPIX + nA);
    float bA = __ldcs(rgb + 2 * NPIX + nA);
    float rB = 0.f, gB = 0.f, bB = 0.f;
    if (hasB) {
        rB = __ldcs(rgb + nB);
        gB = __ldcs(rgb + NPIX + nB);
        bB = __ldcs(rgb + 2 * NPIX + nB);
    }

    // ---- block-uniform y lerp ----
    float gyv = (float)row * SY;
    float fy  = floorf(gyv);
    float wy  = gyv - fy;
    int y0 = min((int)fy, GY - 1);
    int y1 = min(y0 + 1, GY - 1);
    float wy0 = 1.0f - wy, wy1 = wy;

    const float* grid = grids + (size_t)idxp[0] * (GY * GX * GW * 12);
    int xbase = (int)((float)xpix0 * SX);

    // ---- vectorized g2 build: 144 float4 items, single pass w/ 256 threads ----
    if (tid < NC * GW * 3) {
        int xq  = tid / (GW * 3);
        int rem = tid - xq * (GW * 3);
        int zq  = rem / 3;
        int c4  = rem - zq * 3;
        int xc  = min(xbase + xq, GX - 1);
        const float4* pa = reinterpret_cast<const float4*>(
            grid + ((size_t)(y0 * GX + xc) * GW + zq) * 12) + c4;
        const float4* pb = reinterpret_cast<const float4*>(
            grid + ((size_t)(y1 * GX + xc) * GW + zq) * 12) + c4;
        float4 a = __ldg(pa);
        float4 b = __ldg(pb);
        float4 o;
        o.x = wy0 * a.x + wy1 * b.x;
        o.y = wy0 * a.y + wy1 * b.y;
        o.z = wy0 * a.z + wy1 * b.z;
        o.w = wy0 * a.w + wy1 * b.w;
        reinterpret_cast<float4*>(g2)[tid] = o;
    }
    __syncthreads();

    #pragma unroll
    for (int k = 0; k < PXT; k++) {
        const int x = x0p + k * BX;
        if (k == 1 && !hasB) break;
        const int n = row * W_IMG + x;

        float r = (k == 0) ? rA : rB;
        float g = (k == 0) ? gA : gB;
        float b = (k == 0) ? bA : bB;

        float gray = 0.299f * r + 0.587f * g + 0.114f * b;

        float gxv = (float)x * SX;
        float fx  = floorf(gxv);
        float wx  = gxv - fx;
        int xc0 = min((int)fx, GX - 1);
        int xc1 = min(xc0 + 1, GX - 1);
        int x0l = xc0 - xbase;
        int x1l = xc1 - xbase;

        float gz = __saturatef(gray) * (float)(GW - 1);
        float fz = floorf(gz);
        float wz = gz - fz;
        int z0 = min(max((int)fz, 0), GW - 1);
        int z1 = min(z0 + 1, GW - 1);

        float w00 = (1.0f - wx) * (1.0f - wz);
        float w01 = (1.0f - wx) * wz;
        float w10 = wx * (1.0f - wz);
        float w11 = wx * wz;

        const float4* c00 = reinterpret_cast<const float4*>(g2 + (x0l * GW + z0) * 12);
        const float4* c01 = reinterpret_cast<const float4*>(g2 + (x0l * GW + z1) * 12);
        const float4* c10 = reinterpret_cast<const float4*>(g2 + (x1l * GW + z0) * 12);
        const float4* c11 = reinterpret_cast<const float4*>(g2 + (x1l * GW + z1) * 12);

        float4 a0, a1, a2;
        {
            float4 p00, p01, p10, p11;
            p00 = c00[0]; p01 = c01[0]; p10 = c10[0]; p11 = c11[0];
            a0.x = w00*p00.x + w01*p01.x + w10*p10.x + w11*p11.x;
            a0.y = w00*p00.y + w01*p01.y + w10*p10.y + w11*p11.y;
            a0.z = w00*p00.z + w01*p01.z + w10*p10.z + w11*p11.z;
            a0.w = w00*p00.w + w01*p01.w + w10*p10.w + w11*p11.w;
            p00 = c00[1]; p01 = c01[1]; p10 = c10[1]; p11 = c11[1];
            a1.x = w00*p00.x + w01*p01.x + w10*p10.x + w11*p11.x;
            a1.y = w00*p00.y + w01*p01.y + w10*p10.y + w11*p11.y;
            a1.z = w00*p00.z + w01*p01.z + w10*p10.z + w11*p11.z;
            a1.w = w00*p00.w + w01*p01.w + w10*p10.w + w11*p11.w;
            p00 = c00[2]; p01 = c01[2]; p10 = c10[2]; p11 = c11[2];
            a2.x = w00*p00.x + w01*p01.x + w10*p10.x + w11*p11.x;
            a2.y = w00*p00.y + w01*p01.y + w10*p10.y + w11*p11.y;
            a2.z = w00*p00.z + w01*p01.z + w10*p10.z + w11*p11.z;
            a2.w = w00*p00.w + w01*p01.w + w10*p10.w + w11*p11.w;
        }

        // affine out: lane-adjacent pixels -> dense 48B/lane stride, streaming
        float4* aout = reinterpret_cast<float4*>(out) + (size_t)n * 3;
        __stcs(aout + 0, a0);
        __stcs(aout + 1, a1);
        __stcs(aout + 2, a2);

        // res out: scalar stride-3 (3 lines per wavefront), streaming
        float* res = out + (size_t)12 * NPIX + (size_t)n * 3;
        __stcs(res + 0, a0.x * r + a0.y * g + a0.z * b + a0.w);
        __stcs(res + 1, a1.x * r + a1.y * g + a1.z * b + a1.w);
        __stcs(res + 2, a2.x * r + a2.y * g + a2.z * b + a2.w);
    }
}

extern "C" void kernel_launch(void* const* d_in, const int* in_sizes, int n_in,
                              void* d_out, int out_size) {
    const float* rgb   = (const float*)d_in[0];
    const float* grids = (const float*)d_in[1];
    const int*   idx   = (const int*)d_in[2];
    float* out = (float*)d_out;

    dim3 grid((W_IMG + STRIP - 1) / STRIP, H_IMG);   // 4 x 1080
    bilateral_grid_kernel<<<grid, BX>>>(rgb, grids, idx, out);
}

// round 6
// speedup vs baseline: 1.8676x; 1.0662x over previous
#include <cuda_runtime.h>
#include <cuda_fp16.h>

#define H_IMG 1080
#define W_IMG 1920
#define GY 16
#define GX 16
#define GW 8
#define NPIX (H_IMG * W_IMG)

#define BX 256                  // threads per block
#define PXT 2                   // pixels per thread, strided by BX
#define STRIP (BX * PXT)        // 512 pixels per strip
#define NC 6                    // x-cells covered by one strip

#define SX (15.0f / 1919.0f)
#define SY (15.0f / 1079.0f)

__device__ __forceinline__ float2 h2f(unsigned u) {
    __half2 h;
    *reinterpret_cast<unsigned*>(&h) = u;
    return __half22float2(h);
}

__global__ __launch_bounds__(BX) void bilateral_grid_kernel(
    const float* __restrict__ rgb,
    const float* __restrict__ grids,
    const int*   __restrict__ idxp,
    float*       __restrict__ out)
{
    // fp16 y-lerped slab: NC*GW cells x 12 halfs (24B/cell) = 1152 B
    __shared__ __align__(16) __half2 g2h[NC * GW * 6];

    const int tid   = threadIdx.x;
    const int row   = blockIdx.y;
    const int xpix0 = blockIdx.x * STRIP;

    // ---- prefetch rgb early (lane-adjacent -> coalesced) ----
    const int x0p = xpix0 + tid;
    const int nA  = row * W_IMG + x0p;
    const int nB  = nA + BX;
    bool hasB = (x0p + BX < W_IMG);

    float rA = __ldcs(rgb + nA);
    float gA = __ldcs(rgb + NPIX + nA);
    float bA = __ldcs(rgb + 2 * NPIX + nA);
    float rB = 0.f, gB = 0.f, bB = 0.f;
    if (hasB) {
        rB = __ldcs(rgb + nB);
        gB = __ldcs(rgb + NPIX + nB);
        bB = __ldcs(rgb + 2 * NPIX + nB);
    }

    // ---- block-uniform y lerp ----
    float gyv = (float)row * SY;
    float fy  = floorf(gyv);
    float wy  = gyv - fy;
    int y0 = min((int)fy, GY - 1);
    int y1 = min(y0 + 1, GY - 1);
    float wy0 = 1.0f - wy, wy1 = wy;

    const float* grid = grids + (size_t)idxp[0] * (GY * GX * GW * 12);
    int xbase = (int)((float)xpix0 * SX);

    // ---- build g2h: 144 items (cell, float4-chunk), one pass ----
    if (tid < NC * GW * 3) {
        int cell = tid / 3;
        int c4   = tid - cell * 3;
        int xq   = cell / GW;
        int zq   = cell - xq * GW;
        int xc   = min(xbase + xq, GX - 1);
        const float4* pa = reinterpret_cast<const float4*>(
            grid + ((size_t)(y0 * GX + xc) * GW + zq) * 12) + c4;
        const float4* pb = reinterpret_cast<const float4*>(
            grid + ((size_t)(y1 * GX + xc) * GW + zq) * 12) + c4;
        float4 a = __ldg(pa);
        float4 b = __ldg(pb);
        float4 o;
        o.x = wy0 * a.x + wy1 * b.x;
        o.y = wy0 * a.y + wy1 * b.y;
        o.z = wy0 * a.z + wy1 * b.z;
        o.w = wy0 * a.w + wy1 * b.w;
        __half2 h0 = __floats2half2_rn(o.x, o.y);
        __half2 h1 = __floats2half2_rn(o.z, o.w);
        uint2 pk;
        pk.x = *reinterpret_cast<unsigned*>(&h0);
        pk.y = *reinterpret_cast<unsigned*>(&h1);
        reinterpret_cast<uint2*>(g2h)[tid] = pk;   // uint2 index == cell*3 + c4
    }
    __syncthreads();

    const uint2* P = reinterpret_cast<const uint2*>(g2h);

    #pragma unroll
    for (int k = 0; k < PXT; k++) {
        if (k == 1 && !hasB) break;
        const int x = x0p + k * BX;
        const int n = row * W_IMG + x;

        float r = (k == 0) ? rA : rB;
        float g = (k == 0) ? gA : gB;
        float b = (k == 0) ? bA : bB;

        float gray = 0.299f * r + 0.587f * g + 0.114f * b;

        float gxv = (float)x * SX;
        float fx  = floorf(gxv);
        float wx  = gxv - fx;
        int xc0 = min((int)fx, GX - 1);
        int xc1 = min(xc0 + 1, GX - 1);
        int x0l = xc0 - xbase;
        int x1l = xc1 - xbase;

        float gz = __saturatef(gray) * (float)(GW - 1);
        float fz = floorf(gz);
        float wz = gz - fz;
        int z0 = min(max((int)fz, 0), GW - 1);
        int z1 = min(z0 + 1, GW - 1);

        float w00 = (1.0f - wx) * (1.0f - wz);
        float w01 = (1.0f - wx) * wz;
        float w10 = wx * (1.0f - wz);
        float w11 = wx * wz;

        int i00 = (x0l * GW + z0) * 3;
        int i01 = (x0l * GW + z1) * 3;
        int i10 = (x1l * GW + z0) * 3;
        int i11 = (x1l * GW + z1) * 3;

        // issue all 12 LDS.64 up front for MLP
        uint2 qa0 = P[i00], qa1 = P[i00 + 1], qa2 = P[i00 + 2];
        uint2 qb0 = P[i01], qb1 = P[i01 + 1], qb2 = P[i01 + 2];
        uint2 qc0 = P[i10], qc1 = P[i10 + 1], qc2 = P[i10 + 2];
        uint2 qd0 = P[i11], qd1 = P[i11 + 1], qd2 = P[i11 + 2];

        float acc[12];
        #pragma unroll
        for (int j = 0; j < 12; j++) acc[j] = 0.0f;

        #define CORNER(w, q0, q1, q2)                                        \
        {                                                                    \
            float2 f;                                                        \
            f = h2f((q0).x); acc[0]  += (w) * f.x; acc[1]  += (w) * f.y;     \
            f = h2f((q0).y); acc[2]  += (w) * f.x; acc[3]  += (w) * f.y;     \
            f = h2f((q1).x); acc[4]  += (w) * f.x; acc[5]  += (w) * f.y;     \
            f = h2f((q1).y); acc[6]  += (w) * f.x; acc[7]  += (w) * f.y;     \
            f = h2f((q2).x); acc[8]  += (w) * f.x; acc[9]  += (w) * f.y;     \
            f = h2f((q2).y); acc[10] += (w) * f.x; acc[11] += (w) * f.y;     \
        }
        CORNER(w00, qa0, qa1, qa2)
        CORNER(w01, qb0, qb1, qb2)
        CORNER(w10, qc0, qc1, qc2)
        CORNER(w11, qd0, qd1, qd2)
        #undef CORNER

        float4 a0 = make_float4(acc[0], acc[1], acc[2],  acc[3]);
        float4 a1 = make_float4(acc[4], acc[5], acc[6],  acc[7]);
        float4 a2 = make_float4(acc[8], acc[9], acc[10], acc[11]);

        // affine out: lane-adjacent -> dense STG.128, streaming
        float4* aout = reinterpret_cast<float4*>(out) + (size_t)n * 3;
        __stcs(aout + 0, a0);
        __stcs(aout + 1, a1);
        __stcs(aout + 2, a2);

        // res out: scalar stride-3, streaming
        float* res = out + (size_t)12 * NPIX + (size_t)n * 3;
        __stcs(res + 0, a0.x * r + a0.y * g + a0.z * b + a0.w);
        __stcs(res + 1, a1.x * r + a1.y * g + a1.z * b + a1.w);
        __stcs(res + 2, a2.x * r + a2.y * g + a2.z * b + a2.w);
    }
}

extern "C" void kernel_launch(void* const* d_in, const int* in_sizes, int n_in,
                              void* d_out, int out_size) {
    const float* rgb   = (const float*)d_in[0];
    const float* grids = (const float*)d_in[1];
    const int*   idx   = (const int*)d_in[2];
    float* out = (float*)d_out;

    dim3 grid((W_IMG + STRIP - 1) / STRIP, H_IMG);   // 4 x 1080
    bilateral_grid_kernel<<<grid, BX>>>(rgb, grids, idx, out);
}